// round 3
// baseline (speedup 1.0000x reference)
#include <cuda_runtime.h>

// Problem constants
#define BB    8
#define SS    256
#define DIMQ  64
#define DD    100
#define SA    255   // rows of a1/a2/r2
#define SO    254   // output rows
#define TEMP_INV 0.1f
#define EPSV  1e-5f

// Scratch (device-global: no allocation allowed in kernel_launch)
__device__ float g_Q1[BB*SS*DD];          // [b][i][d], valid i in [0,254]
__device__ float g_K1[BB*SS*DD];          // [b][j][d]
__device__ float g_r1[BB*SS*SS*DD];       // [b][i][j][c], c fastest
__device__ float g_r2[BB*SS*DD*SS];       // [b][i][d][j], j fastest, valid i in [0,254]

// ---- packed f32x2 helpers (FFMA2: ptxas never auto-fuses; PTX only) ----
__device__ __forceinline__ unsigned long long fma2(unsigned long long a,
                                                   unsigned long long b,
                                                   unsigned long long c) {
    unsigned long long d;
    asm("fma.rn.f32x2 %0, %1, %2, %3;" : "=l"(d) : "l"(a), "l"(b), "l"(c));
    return d;
}
__device__ __forceinline__ unsigned long long pack2(float x) {
    unsigned long long r;
    unsigned u = __float_as_uint(x);
    asm("mov.b64 %0, {%1, %1};" : "=l"(r) : "r"(u));
    return r;
}

// ============================================================
// Kernel 1: Q1[b,d,i] and K1[b,d,j] (conv1 separates: a1 = Q1 + K1 + b1)
// ============================================================
__global__ void prep_kernel(const float* __restrict__ q, const float* __restrict__ k,
                            const float* __restrict__ W1) {
    int b = blockIdx.y;
    int task = blockIdx.x * blockDim.x + threadIdx.x;
    if (blockIdx.z == 0) {
        if (task >= SA*DD) return;
        int i = task / DD, d = task % DD;
        const float* w  = W1 + d*256;                 // W1[d, c, h] at d*256 + c*2 + h
        const float* q0 = q + (b*SS + i)*DIMQ;
        float s = 0.f;
        #pragma unroll 8
        for (int t = 0; t < DIMQ; t++)
            s += q0[t]*w[2*t] + q0[DIMQ + t]*w[2*t+1];
        g_Q1[(b*SS + i)*DD + d] = s;
    } else {
        if (task >= SS*DD) return;
        int j = task / DD, d = task % DD;
        const float* w  = W1 + d*256 + 128;           // k-branch channels 64..127
        const float* k0 = k + (b*SS + j)*DIMQ;
        float s = 0.f;
        #pragma unroll 8
        for (int t = 0; t < DIMQ; t++)
            s += k0[t]*(w[2*t] + w[2*t+1]);
        g_K1[(b*SS + j)*DD + d] = s;
    }
}

// ============================================================
// Kernel 2: r1[b,i,j,c] = relu(bn1(pad(a1)))   (rank-1 + affine + relu)
// Row i=0 is the zero-pad row: pre-activation is exactly 0 -> relu(C1_c).
// ============================================================
__global__ void r1_kernel(const float* __restrict__ b1, const float* __restrict__ g1,
                          const float* __restrict__ be1, const float* __restrict__ m1,
                          const float* __restrict__ var1) {
    int i = blockIdx.x, b = blockIdx.y;
    int c    = threadIdx.x & 127;
    int half = threadIdx.x >> 7;
    if (c >= DD) return;
    float A1 = g1[c] * rsqrtf(var1[c] + EPSV);
    float C1 = be1[c] - A1 * m1[c];
    float* outb = g_r1 + (size_t)((b*SS + i)*SS)*DD + c;
    if (i == 0) {
        float val = fmaxf(C1, 0.f);
        for (int j = half*128; j < half*128 + 128; j++) outb[(size_t)j*DD] = val;
    } else {
        float E = g_Q1[(b*SS + (i-1))*DD + c] + b1[c];
        const float* k1b = g_K1 + (size_t)b*SS*DD + c;
        for (int j = half*128; j < half*128 + 128; j++) {
            float val = fmaxf(fmaf(A1, E + k1b[(size_t)j*DD], C1), 0.f);
            outb[(size_t)j*DD] = val;
        }
    }
}

// ============================================================
// Kernel 3: conv2 GEMM (K=200) + residual + bn2 + relu -> r2[b,i,d,j]
// Block: (jtile of 128) x (one i row) x (b). 256 threads = 16 tx x 16 ty.
//   tx -> 8 j's as 4 lane-consecutive f32x2 pairs (conflict-free LDS.64)
//   ty -> 7 d's strided by 16 (W2 LDS is a 2-address broadcast per warp)
// Whole W2 (80 KB) + both r1 rows (102 KB) live in smem.
// ============================================================
#define SMEM3_FLOATS (2*DD*128 + 2*DD*DD)   // 25600 + 20000 = 45600 floats = 182400 B

__global__ __launch_bounds__(256, 1)
void gemm2_kernel(const float* __restrict__ W2, const float* __restrict__ b2,
                  const float* __restrict__ g2, const float* __restrict__ be2,
                  const float* __restrict__ m2, const float* __restrict__ var2,
                  const float* __restrict__ b1) {
    extern __shared__ float sm[];
    float* r1s = sm;                 // [h][c][128j]
    float* W2s = sm + 2*DD*128;      // [h][c][d]

    int j0 = blockIdx.x * 128;
    int i  = blockIdx.y;
    int b  = blockIdx.z;
    int tid = threadIdx.x;
    int tx = tid & 15, ty = tid >> 4;

    // Load W2 -> W2s[h][c][d]  (global W2[d,c,h] contiguous read, smem scatter)
    for (int lin = tid; lin < 2*DD*DD; lin += 256) {
        int d = lin / 200, rem = lin % 200;
        int c = rem >> 1, h = rem & 1;
        W2s[(h*DD + c)*DD + d] = W2[lin];
    }
    // Load r1 rows i and i+1 (global contiguous; smem transpose to [c][j])
    #pragma unroll
    for (int h = 0; h < 2; h++) {
        const float* src = g_r1 + (size_t)((b*SS + i + h)*SS + j0)*DD;
        float* dst = r1s + h*DD*128;
        for (int lin = tid; lin < 128*DD; lin += 256) {
            int c = lin % DD, j = lin / DD;
            dst[c*128 + j] = src[lin];
        }
    }
    __syncthreads();

    unsigned long long acc[7][4];
    #pragma unroll
    for (int n = 0; n < 7; n++)
        #pragma unroll
        for (int p = 0; p < 4; p++) acc[n][p] = 0ull;

    #pragma unroll 1
    for (int c = 0; c < DD; c++) {
        const unsigned long long* ra0 = (const unsigned long long*)(r1s + c*128);
        const unsigned long long* ra1 = (const unsigned long long*)(r1s + (DD + c)*128);
        unsigned long long a0[4], a1[4];
        #pragma unroll
        for (int p = 0; p < 4; p++) { a0[p] = ra0[tx + 16*p]; a1[p] = ra1[tx + 16*p]; }
        #pragma unroll
        for (int n = 0; n < 7; n++) {
            int d = ty + 16*n; int dd = (d < DD) ? d : 0;
            unsigned long long w0 = pack2(W2s[c*DD + dd]);
            unsigned long long w1 = pack2(W2s[(DD + c)*DD + dd]);
            #pragma unroll
            for (int p = 0; p < 4; p++) {
                acc[n][p] = fma2(a0[p], w0, acc[n][p]);
                acc[n][p] = fma2(a1[p], w1, acc[n][p]);
            }
        }
    }

    // Epilogue: + b2 + residual(Q1+K1+b1) -> bn2 -> relu -> store [b][i][d][j]
    #pragma unroll
    for (int n = 0; n < 7; n++) {
        int d = ty + 16*n;
        if (d >= DD) continue;
        float A2 = g2[d] * rsqrtf(var2[d] + EPSV);
        float C2 = be2[d] - A2 * m2[d];
        float base = b2[d] + b1[d] + g_Q1[(b*SS + i)*DD + d];
        float* dst = g_r2 + (size_t)((b*SS + i)*DD + d)*SS + j0;
        const float* k1b = g_K1 + (size_t)b*SS*DD + d;
        #pragma unroll
        for (int p = 0; p < 4; p++) {
            int jl = 2*(tx + 16*p);
            float lo = __uint_as_float((unsigned)(acc[n][p] & 0xffffffffull));
            float hi = __uint_as_float((unsigned)(acc[n][p] >> 32));
            float t0 = lo + base + k1b[(size_t)(j0 + jl)*DD];
            float t1 = hi + base + k1b[(size_t)(j0 + jl + 1)*DD];
            float2 r;
            r.x = fmaxf(fmaf(A2, t0, C2), 0.f);
            r.y = fmaxf(fmaf(A2, t1, C2), 0.f);
            *(float2*)(dst + jl) = r;
        }
    }
}

// ============================================================
// Kernel 4: conv3 + /TEMP + softmax(j) + attn@v. One block per (b, i).
// r2 layout [b][i][d][j] makes the d-loop loads lane-coalesced.
// Output: [ out (8*254*64) | attn (8*254*256) ]
// ============================================================
__global__ void attn_kernel(const float* __restrict__ W3, const float* __restrict__ b3,
                            const float* __restrict__ v, float* __restrict__ out) {
    int i = blockIdx.x, b = blockIdx.y;
    int tid = threadIdx.x;   // = j
    __shared__ float red[256];
    __shared__ float attn_s[256];
    __shared__ float w3s[2*DD];
    if (tid < 2*DD) w3s[tid] = W3[tid];
    __syncthreads();

    const float* r2a = g_r2 + (size_t)((b*SS + i    )*DD)*SS + tid;
    const float* r2b = g_r2 + (size_t)((b*SS + i + 1)*DD)*SS + tid;
    float a3 = b3[0];
    #pragma unroll 4
    for (int d = 0; d < DD; d++)
        a3 += w3s[2*d]*r2a[(size_t)d*SS] + w3s[2*d+1]*r2b[(size_t)d*SS];
    float logit = a3 * TEMP_INV;

    red[tid] = logit; __syncthreads();
    for (int s = 128; s > 0; s >>= 1) { if (tid < s) red[tid] = fmaxf(red[tid], red[tid+s]); __syncthreads(); }
    float mx = red[0]; __syncthreads();
    float p = expf(logit - mx);
    red[tid] = p; __syncthreads();
    for (int s = 128; s > 0; s >>= 1) { if (tid < s) red[tid] += red[tid+s]; __syncthreads(); }
    float inv = 1.f / red[0]; __syncthreads();

    float a = p * inv;
    attn_s[tid] = a;
    out[(size_t)BB*SO*DIMQ + (size_t)(b*SO + i)*SS + tid] = a;
    __syncthreads();

    // out[b,i,t] = sum_j attn[j] * v[b,j,t] ; 4 j-quarters x 64 t (coalesced on t)
    int t = tid & 63, g = tid >> 6;
    const float* vb = v + (size_t)b*SS*DIMQ + t;
    float acc = 0.f;
    #pragma unroll 4
    for (int j = g*64; j < g*64 + 64; j++) acc += attn_s[j] * vb[(size_t)j*DIMQ];
    red[tid] = acc; __syncthreads();
    if (g == 0)
        out[(size_t)(b*SO + i)*DIMQ + t] = red[t] + red[64+t] + red[128+t] + red[192+t];
}

// ============================================================
extern "C" void kernel_launch(void* const* d_in, const int* in_sizes, int n_in,
                              void* d_out, int out_size) {
    const float* q    = (const float*)d_in[0];
    const float* k    = (const float*)d_in[1];
    const float* v    = (const float*)d_in[2];
    const float* W1   = (const float*)d_in[3];
    const float* b1   = (const float*)d_in[4];
    const float* g1   = (const float*)d_in[5];
    const float* be1  = (const float*)d_in[6];
    const float* m1   = (const float*)d_in[7];
    const float* var1 = (const float*)d_in[8];
    const float* W2   = (const float*)d_in[9];
    const float* b2   = (const float*)d_in[10];
    const float* g2   = (const float*)d_in[11];
    const float* be2  = (const float*)d_in[12];
    const float* m2   = (const float*)d_in[13];
    const float* var2 = (const float*)d_in[14];
    const float* W3   = (const float*)d_in[15];
    const float* b3   = (const float*)d_in[16];
    float* out = (float*)d_out;

    // Idempotent, deterministic, not a stream op — safe under graph capture.
    cudaFuncSetAttribute(gemm2_kernel, cudaFuncAttributeMaxDynamicSharedMemorySize,
                         SMEM3_FLOATS * (int)sizeof(float));

    prep_kernel <<<dim3((SS*DD + 255)/256, BB, 2), 256>>>(q, k, W1);
    r1_kernel   <<<dim3(SS, BB), 256>>>(b1, g1, be1, m1, var1);
    gemm2_kernel<<<dim3(2, SA, BB), 256, SMEM3_FLOATS*sizeof(float)>>>(W2, b2, g2, be2, m2, var2, b1);
    attn_kernel <<<dim3(SO, BB), 256>>>(W3, b3, v, out);
}

// round 9
// speedup vs baseline: 1.9383x; 1.9383x over previous
#include <cuda_runtime.h>
#include <cstdint>

// Problem constants
#define BB    8
#define SS    256
#define DIMQ  64
#define DD    100
#define SA    255   // rows of a2/r2
#define SO    254   // output rows
#define TEMP_INV 0.1f
#define EPSV  1e-5f

// GEMM tiling per (b, i, jtile): D[j=128, d=104] = A[j,k=200] * B[d,k=200]
#define NPAD  104
#define KK    200
#define NT    13      // 104/8 n-tiles
#define KSTEPS 25     // 200/8
#define ASTR  204     // smem row stride (floats); 816 B per row (8B-aligned), 204%32=12 conflict-free
#define BSTR  204
#define CSTR  106     // EVEN -> every row 8B-aligned for float2 staging (105 caused misaligned address)

// Scratch (device globals: no allocation allowed)
__device__ float g_Q1[BB*SS*DD];            // [b][i][d]
__device__ float g_K1T[BB*DD*SS];           // [b][c][j]
__device__ float g_r2[(size_t)BB*SS*DD*SS]; // [b][i][d][j]
__device__ uint32_t g_Btf[NPAD*KK];         // W2 padded to 104 rows, tf32-converted
__device__ float g_A1f[DD], g_C1f[DD], g_A2f[DD], g_C2f[DD], g_b12[DD];

// ---------------- helpers ----------------
__device__ __forceinline__ uint32_t f2tf32(float x) {
    uint32_t u;
    asm("cvt.rna.tf32.f32 %0, %1;" : "=r"(u) : "f"(x));
    return u;
}
__device__ __forceinline__ void mma_tf32(float* c, uint32_t a0, uint32_t a1, uint32_t a2,
                                         uint32_t a3, uint32_t b0, uint32_t b1) {
    asm volatile(
        "mma.sync.aligned.m16n8k8.row.col.f32.tf32.tf32.f32 "
        "{%0,%1,%2,%3}, {%4,%5,%6,%7}, {%8,%9}, {%0,%1,%2,%3};"
        : "+f"(c[0]), "+f"(c[1]), "+f"(c[2]), "+f"(c[3])
        : "r"(a0), "r"(a1), "r"(a2), "r"(a3), "r"(b0), "r"(b1));
}

// ============================================================
// Kernel 0: params — bn folds + tf32-converted padded W2 image
// ============================================================
__global__ void params_kernel(const float* __restrict__ W2,
                              const float* __restrict__ b1, const float* __restrict__ b2,
                              const float* __restrict__ g1, const float* __restrict__ be1,
                              const float* __restrict__ m1, const float* __restrict__ var1,
                              const float* __restrict__ g2, const float* __restrict__ be2,
                              const float* __restrict__ m2, const float* __restrict__ var2) {
    int tid = threadIdx.x;
    if (tid < DD) {
        float A1 = g1[tid] * rsqrtf(var1[tid] + EPSV);
        g_A1f[tid] = A1; g_C1f[tid] = be1[tid] - A1 * m1[tid];
        float A2 = g2[tid] * rsqrtf(var2[tid] + EPSV);
        g_A2f[tid] = A2; g_C2f[tid] = be2[tid] - A2 * m2[tid];
        g_b12[tid] = b1[tid] + b2[tid];
    }
    for (int t = tid; t < NPAD * KK; t += blockDim.x) {
        int n = t / KK, k = t % KK;
        float v = (n < DD) ? W2[n * KK + k] : 0.f;
        g_Btf[t] = f2tf32(v);
    }
}

// ============================================================
// Kernel 1: Q1[b][i][d], K1T[b][c][j]  (conv1 separates)
// ============================================================
__global__ void prep_kernel(const float* __restrict__ q, const float* __restrict__ k,
                            const float* __restrict__ W1) {
    int b = blockIdx.y;
    int task = blockIdx.x * blockDim.x + threadIdx.x;
    if (blockIdx.z == 0) {
        if (task >= SA*DD) return;
        int i = task / DD, d = task % DD;
        const float* w  = W1 + d*256;
        const float* q0 = q + (b*SS + i)*DIMQ;
        float s = 0.f;
        #pragma unroll 8
        for (int t = 0; t < DIMQ; t++)
            s += q0[t]*w[2*t] + q0[DIMQ + t]*w[2*t+1];
        g_Q1[(b*SS + i)*DD + d] = s;
    } else {
        if (task >= SS*DD) return;
        int j = task / DD, d = task % DD;
        const float* w  = W1 + d*256 + 128;
        const float* k0 = k + (b*SS + j)*DIMQ;
        float s = 0.f;
        #pragma unroll 8
        for (int t = 0; t < DIMQ; t++)
            s += k0[t]*(w[2*t] + w[2*t+1]);
        g_K1T[(b*DD + d)*SS + j] = s;
    }
}

// ============================================================
// Kernel 2: mma.sync tf32 GEMM + fused epilogue.
// One CTA per (jtile, i, b): 256 threads = 8 warps, warp tile = 16j x 104d.
//  A[128j][200k] generated on the fly (r1 never materialized), tf32 in smem
//  B[104d][200k] copied from pre-converted g_Btf
//  Epilogue: +b2 +residual(Q1+K1+b1) -> bn2 -> relu -> g_r2[b][i][d][j]
// ============================================================
#define SM_AS 0
#define SM_BS (128*ASTR)                 // 26112 floats
#define SM_PP (SM_BS + NPAD*BSTR)       // +21216 = 47328
#define SM_FLOATS (SM_PP + 7*NPAD)      // +728 = 48056 floats = 192224 B

__global__ __launch_bounds__(256, 1)
void gemm2_mma(const float* __restrict__ b1) {
    extern __shared__ float sm[];
    float* As = sm + SM_AS;          // [128][ASTR], tf32 bits
    float* Bs = sm + SM_BS;          // [104][BSTR], tf32 bits
    float* Eb0 = sm + SM_PP;
    float* Eb1 = Eb0 + NPAD;
    float* A1s = Eb0 + 2*NPAD;
    float* A1z = Eb0 + 3*NPAD;
    float* Fb  = Eb0 + 4*NPAD;
    float* A2s = Eb0 + 5*NPAD;
    float* C2s = Eb0 + 6*NPAD;

    int tid = threadIdx.x, wid = tid >> 5, lane = tid & 31;
    int j0 = blockIdx.x * 128, i = blockIdx.y, b = blockIdx.z;

    // ---- B: copy pre-converted tf32 image (L2-hot), [d][k] -> stride BSTR ----
    for (int t = tid; t < NPAD*KK; t += 256) {
        int d = t / KK, k = t % KK;
        ((uint32_t*)Bs)[d*BSTR + k] = g_Btf[t];
    }
    // ---- per-CTA folded params ----
    if (tid < DD) {
        float A1 = g_A1f[tid], C1 = g_C1f[tid];
        float bb = b1[tid];
        Eb1[tid] = fmaf(A1, g_Q1[(b*SS + i)*DD + tid] + bb, C1);
        Eb0[tid] = (i > 0) ? fmaf(A1, g_Q1[(b*SS + i - 1)*DD + tid] + bb, C1) : C1;
        A1s[tid] = A1;
        A1z[tid] = (i > 0) ? A1 : 0.f;
        Fb[tid]  = g_b12[tid] + g_Q1[(b*SS + i)*DD + tid];
        A2s[tid] = g_A2f[tid];
        C2s[tid] = g_C2f[tid];
    }
    __syncthreads();

    // ---- A generation: r1 rows on the fly, tf32, As[j][k=2c+h] ----
    {
        int j = tid & 127, half = tid >> 7;
        const float* kcol = g_K1T + (size_t)b*DD*SS + j0 + j;
        uint32_t* arow = (uint32_t*)(As + j*ASTR);
        #pragma unroll 5
        for (int c = half*50; c < half*50 + 50; c++) {
            float kv = kcol[(size_t)c*SS];
            float v0 = fmaxf(fmaf(A1z[c], kv, Eb0[c]), 0.f);
            float v1 = fmaxf(fmaf(A1s[c], kv, Eb1[c]), 0.f);
            uint2 u; u.x = f2tf32(v0); u.y = f2tf32(v1);
            *(uint2*)(arow + 2*c) = u;
        }
    }
    __syncthreads();

    // ---- MMA mainloop: warp tile 16j x 104d ----
    float C[NT][4];
    #pragma unroll
    for (int nt = 0; nt < NT; nt++)
        #pragma unroll
        for (int r = 0; r < 4; r++) C[nt][r] = 0.f;

    {
        int ly = lane >> 2, lx = lane & 3;       // groupID, tid-in-group
        int jw = wid * 16;
        const uint32_t* Au = (const uint32_t*)As;
        const uint32_t* Bu = (const uint32_t*)Bs;
        const uint32_t* arow0 = Au + (jw + ly)*ASTR;
        const uint32_t* arow1 = Au + (jw + ly + 8)*ASTR;
        const uint32_t* brow  = Bu + ly*BSTR;    // + nt*8*BSTR per n-tile
        #pragma unroll 5
        for (int ks = 0; ks < KSTEPS; ks++) {
            int k0 = 8*ks;
            uint32_t a0 = arow0[k0 + lx];
            uint32_t a1 = arow1[k0 + lx];
            uint32_t a2 = arow0[k0 + lx + 4];
            uint32_t a3 = arow1[k0 + lx + 4];
            #pragma unroll
            for (int nt = 0; nt < NT; nt++) {
                uint32_t b0 = brow[nt*8*BSTR + k0 + lx];
                uint32_t b1v = brow[nt*8*BSTR + k0 + lx + 4];
                mma_tf32(C[nt], a0, a1, a2, a3, b0, b1v);
            }
        }
    }
    __syncthreads();   // all warps done reading As before Cs overwrites it

    // ---- stage C to smem (reuse As region): Cs[j][d] stride CSTR (even -> 8B-aligned rows) ----
    {
        float* Cs = As;
        int ly = lane >> 2, lx = lane & 3;
        int jw = wid * 16;
        #pragma unroll
        for (int nt = 0; nt < NT; nt++) {
            int col = 8*nt + 2*lx;
            *(float2*)(Cs + (jw + ly    )*CSTR + col) = make_float2(C[nt][0], C[nt][1]);
            *(float2*)(Cs + (jw + ly + 8)*CSTR + col) = make_float2(C[nt][2], C[nt][3]);
        }
    }
    __syncthreads();

    // ---- epilogue: residual + bn2 + relu, coalesced stores ----
    {
        const float* Cs = As;
        int jrow = tid & 127, dhalf = tid >> 7;
        float* dst = g_r2 + ((size_t)(b*SS + i)*DD)*SS + j0 + jrow;
        const float* kcol = g_K1T + (size_t)b*DD*SS + j0 + jrow;
        #pragma unroll 5
        for (int d = dhalf*50; d < dhalf*50 + 50; d++) {
            float t = Cs[jrow*CSTR + d] + Fb[d] + kcol[(size_t)d*SS];
            dst[(size_t)d*SS] = fmaxf(fmaf(A2s[d], t, C2s[d]), 0.f);
        }
    }
}

// ============================================================
// Kernel 3: conv3 + /TEMP + softmax(j) + attn@v. One block per (b, i).
// Output: [ out (8*254*64) | attn (8*254*256) ]
// ============================================================
__global__ void attn_kernel(const float* __restrict__ W3, const float* __restrict__ b3,
                            const float* __restrict__ v, float* __restrict__ out) {
    int i = blockIdx.x, b = blockIdx.y;
    int tid = threadIdx.x;   // = j
    __shared__ float red[256];
    __shared__ float attn_s[256];
    __shared__ float w3s[2*DD];
    if (tid < 2*DD) w3s[tid] = W3[tid];
    __syncthreads();

    const float* r2a = g_r2 + ((size_t)(b*SS + i    )*DD)*SS + tid;
    const float* r2b = g_r2 + ((size_t)(b*SS + i + 1)*DD)*SS + tid;
    float a3 = b3[0];
    #pragma unroll 4
    for (int d = 0; d < DD; d++)
        a3 += w3s[2*d]*r2a[(size_t)d*SS] + w3s[2*d+1]*r2b[(size_t)d*SS];
    float logit = a3 * TEMP_INV;

    red[tid] = logit; __syncthreads();
    for (int s = 128; s > 0; s >>= 1) { if (tid < s) red[tid] = fmaxf(red[tid], red[tid+s]); __syncthreads(); }
    float mx = red[0]; __syncthreads();
    float p = expf(logit - mx);
    red[tid] = p; __syncthreads();
    for (int s = 128; s > 0; s >>= 1) { if (tid < s) red[tid] += red[tid+s]; __syncthreads(); }
    float inv = 1.f / red[0]; __syncthreads();

    float a = p * inv;
    attn_s[tid] = a;
    out[(size_t)BB*SO*DIMQ + (size_t)(b*SO + i)*SS + tid] = a;
    __syncthreads();

    int t = tid & 63, g = tid >> 6;
    const float* vb = v + (size_t)b*SS*DIMQ + t;
    float acc = 0.f;
    #pragma unroll 4
    for (int j = g*64; j < g*64 + 64; j++) acc += attn_s[j] * vb[(size_t)j*DIMQ];
    red[tid] = acc; __syncthreads();
    if (g == 0)
        out[(size_t)(b*SO + i)*DIMQ + t] = red[t] + red[64+t] + red[128+t] + red[192+t];
}

// ============================================================
extern "C" void kernel_launch(void* const* d_in, const int* in_sizes, int n_in,
                              void* d_out, int out_size) {
    const float* q    = (const float*)d_in[0];
    const float* k    = (const float*)d_in[1];
    const float* v    = (const float*)d_in[2];
    const float* W1   = (const float*)d_in[3];
    const float* b1   = (const float*)d_in[4];
    const float* g1   = (const float*)d_in[5];
    const float* be1  = (const float*)d_in[6];
    const float* m1   = (const float*)d_in[7];
    const float* var1 = (const float*)d_in[8];
    const float* W2   = (const float*)d_in[9];
    const float* b2   = (const float*)d_in[10];
    const float* g2   = (const float*)d_in[11];
    const float* be2  = (const float*)d_in[12];
    const float* m2   = (const float*)d_in[13];
    const float* var2 = (const float*)d_in[14];
    const float* W3   = (const float*)d_in[15];
    const float* b3   = (const float*)d_in[16];
    float* out = (float*)d_out;

    cudaFuncSetAttribute(gemm2_mma, cudaFuncAttributeMaxDynamicSharedMemorySize,
                         SM_FLOATS * (int)sizeof(float));

    params_kernel<<<1, 256>>>(W2, b1, b2, g1, be1, m1, var1, g2, be2, m2, var2);
    prep_kernel  <<<dim3((SS*DD + 255)/256, BB, 2), 256>>>(q, k, W1);
    gemm2_mma    <<<dim3(2, SA, BB), 256, SM_FLOATS*sizeof(float)>>>(b1);
    attn_kernel  <<<dim3(SO, BB), 256>>>(W3, b3, v, out);
}

// round 10
// speedup vs baseline: 3.7667x; 1.9433x over previous
#include <cuda_runtime.h>
#include <cuda_fp16.h>
#include <cstdint>

// Problem constants
#define BB    8
#define SS    256
#define DIMQ  64
#define DD    100
#define SA    255   // rows of a2/r2
#define SO    254   // output rows
#define TEMP_INV 0.1f
#define EPSV  1e-5f

// GEMM tiling per (b, i, jtile): D[j=128, d=104] = A[j,k] * B[d,k], K padded 200->208 (fp16)
#define NPAD  104
#define KK    200
#define NT    13      // 104/8 n-tiles
#define KS16  13      // 208/16 k-steps
#define K2    104     // packed half2 words per row (208 halves)
#define AS2   108     // smem row stride in u32; 108%32=12 -> conflict-free frag loads
#define BS2   108
#define CSTR  106     // even -> 8B-aligned float2 staging rows

// Scratch (device globals: no allocation allowed)
__device__ float g_Q1[BB*SS*DD];            // [b][i][d]
__device__ float g_K1T[BB*DD*SS];           // [b][c][j]
__device__ float g_P0[BB*SS*SS];            // conv3 partial, h=0 tap
__device__ float g_P1[BB*SS*SS];            // conv3 partial, h=1 tap
__device__ uint32_t g_Bh[NPAD*K2];          // W2 padded, packed half2
__device__ float g_A1f[DD], g_C1f[DD], g_A2f[DD], g_C2f[DD], g_b12[DD];

// ---------------- helpers ----------------
__device__ __forceinline__ uint32_t packh2(float a, float b) {
    __half2 h = __floats2half2_rn(a, b);
    return *(uint32_t*)&h;
}
__device__ __forceinline__ void mma_f16(float* c, uint32_t a0, uint32_t a1, uint32_t a2,
                                        uint32_t a3, uint32_t b0, uint32_t b1) {
    asm volatile(
        "mma.sync.aligned.m16n8k16.row.col.f32.f16.f16.f32 "
        "{%0,%1,%2,%3}, {%4,%5,%6,%7}, {%8,%9}, {%0,%1,%2,%3};"
        : "+f"(c[0]), "+f"(c[1]), "+f"(c[2]), "+f"(c[3])
        : "r"(a0), "r"(a1), "r"(a2), "r"(a3), "r"(b0), "r"(b1));
}

// ============================================================
// Kernel 0: params — bn folds + fp16-packed padded W2 image
// ============================================================
__global__ void params_kernel(const float* __restrict__ W2,
                              const float* __restrict__ b1, const float* __restrict__ b2,
                              const float* __restrict__ g1, const float* __restrict__ be1,
                              const float* __restrict__ m1, const float* __restrict__ var1,
                              const float* __restrict__ g2, const float* __restrict__ be2,
                              const float* __restrict__ m2, const float* __restrict__ var2) {
    int tid = threadIdx.x;
    if (tid < DD) {
        float A1 = g1[tid] * rsqrtf(var1[tid] + EPSV);
        g_A1f[tid] = A1; g_C1f[tid] = be1[tid] - A1 * m1[tid];
        float A2 = g2[tid] * rsqrtf(var2[tid] + EPSV);
        g_A2f[tid] = A2; g_C2f[tid] = be2[tid] - A2 * m2[tid];
        g_b12[tid] = b1[tid] + b2[tid];
    }
    for (int t = tid; t < NPAD * K2; t += blockDim.x) {
        int n = t / K2, k2 = t % K2;
        int k = 2*k2;
        float v0 = (n < DD && k     < KK) ? W2[n*KK + k]     : 0.f;
        float v1 = (n < DD && k + 1 < KK) ? W2[n*KK + k + 1] : 0.f;
        g_Bh[t] = packh2(v0, v1);
    }
}

// ============================================================
// Kernel 1: Q1[b][i][d], K1T[b][c][j]  (conv1 separates)
// ============================================================
__global__ void prep_kernel(const float* __restrict__ q, const float* __restrict__ k,
                            const float* __restrict__ W1) {
    int b = blockIdx.y;
    int task = blockIdx.x * blockDim.x + threadIdx.x;
    if (blockIdx.z == 0) {
        if (task >= SA*DD) return;
        int i = task / DD, d = task % DD;
        const float* w  = W1 + d*256;
        const float* q0 = q + (b*SS + i)*DIMQ;
        float s = 0.f;
        #pragma unroll 8
        for (int t = 0; t < DIMQ; t++)
            s += q0[t]*w[2*t] + q0[DIMQ + t]*w[2*t+1];
        g_Q1[(b*SS + i)*DD + d] = s;
    } else {
        if (task >= SS*DD) return;
        int j = task / DD, d = task % DD;
        const float* w  = W1 + d*256 + 128;
        const float* k0 = k + (b*SS + j)*DIMQ;
        float s = 0.f;
        #pragma unroll 8
        for (int t = 0; t < DIMQ; t++)
            s += k0[t]*(w[2*t] + w[2*t+1]);
        g_K1T[(b*DD + d)*SS + j] = s;
    }
}

// ============================================================
// Kernel 2: fp16 mma.sync GEMM + fused bn2/relu/conv3 epilogue.
// One CTA per (jtile, i, b): 256 threads = 8 warps, warp tile = 16j x 104d.
//  A[128j][208k] fp16 generated on the fly (r1 never materialized)
//  B[104d][208k] fp16 copied from pre-packed g_Bh
//  Epilogue: r2 = relu(bn2(C + residual)) kept LOCAL; emit conv3 partials P0/P1.
// ============================================================
#define SM_A  0                       // u32 Apk[128][AS2] = 13824 words
#define SM_B  (128*AS2)               // u32 Bpk[104][BS2] = 11232 words
#define SM_P  (SM_B + NPAD*BS2)       // 25056
#define SM_WORDS (SM_P + 9*NPAD)      // +936 = 25992 words = 103968 B  (x2 CTAs = 208KB)

__global__ __launch_bounds__(256, 2)
void gemm2_mma(const float* __restrict__ b1, const float* __restrict__ W3) {
    extern __shared__ float sm[];
    uint32_t* Apk = (uint32_t*)sm;             // [128][AS2]
    uint32_t* Bpk = (uint32_t*)sm + SM_B;      // [104][BS2]
    float* Eb0 = sm + SM_P;
    float* Eb1 = Eb0 + NPAD;
    float* A1s = Eb0 + 2*NPAD;
    float* A1z = Eb0 + 3*NPAD;
    float* Fb  = Eb0 + 4*NPAD;
    float* A2s = Eb0 + 5*NPAD;
    float* C2s = Eb0 + 6*NPAD;
    float* W30 = Eb0 + 7*NPAD;
    float* W31 = Eb0 + 8*NPAD;

    int tid = threadIdx.x, wid = tid >> 5, lane = tid & 31;
    int j0 = blockIdx.x * 128, i = blockIdx.y, b = blockIdx.z;

    // ---- B: copy pre-packed fp16 image (L2-hot) ----
    for (int t = tid; t < NPAD*K2; t += 256) {
        int d = t / K2, k2 = t % K2;
        Bpk[d*BS2 + k2] = g_Bh[t];
    }
    // ---- per-CTA folded params ----
    if (tid < DD) {
        float A1 = g_A1f[tid], C1 = g_C1f[tid];
        float bb = b1[tid];
        Eb1[tid] = fmaf(A1, g_Q1[(b*SS + i)*DD + tid] + bb, C1);
        Eb0[tid] = (i > 0) ? fmaf(A1, g_Q1[(b*SS + i - 1)*DD + tid] + bb, C1) : C1;
        A1s[tid] = A1;
        A1z[tid] = (i > 0) ? A1 : 0.f;
        Fb[tid]  = g_b12[tid] + g_Q1[(b*SS + i)*DD + tid];
        A2s[tid] = g_A2f[tid];
        C2s[tid] = g_C2f[tid];
        W30[tid] = W3[2*tid];
        W31[tid] = W3[2*tid + 1];
    }
    __syncthreads();

    // ---- A generation: r1 rows on the fly, fp16-packed, Apk[j][k2=c] ----
    {
        int j = tid & 127, half = tid >> 7;
        const float* kcol = g_K1T + (size_t)b*DD*SS + j0 + j;
        uint32_t* arow = Apk + j*AS2;
        #pragma unroll 5
        for (int c = half*50; c < half*50 + 50; c++) {
            float kv = kcol[(size_t)c*SS];
            float v0 = fmaxf(fmaf(A1z[c], kv, Eb0[c]), 0.f);
            float v1 = fmaxf(fmaf(A1s[c], kv, Eb1[c]), 0.f);
            arow[c] = packh2(v0, v1);
        }
        // zero K-pad words k2 in [100,104)
        arow[100 + half*2]     = 0u;
        arow[100 + half*2 + 1] = 0u;
    }
    __syncthreads();

    // ---- MMA mainloop: warp tile 16j x 104d, m16n8k16 fp16 ----
    float C[NT][4];
    #pragma unroll
    for (int nt = 0; nt < NT; nt++)
        #pragma unroll
        for (int r = 0; r < 4; r++) C[nt][r] = 0.f;

    {
        int ly = lane >> 2, lx = lane & 3;       // groupID, tid-in-group
        int jw = wid * 16;
        const uint32_t* arow0 = Apk + (jw + ly)*AS2;
        const uint32_t* arow1 = Apk + (jw + ly + 8)*AS2;
        const uint32_t* brow  = Bpk + ly*BS2;
        #pragma unroll
        for (int ks = 0; ks < KS16; ks++) {
            int k2b = 8*ks;
            uint32_t a0 = arow0[k2b + lx];
            uint32_t a1 = arow1[k2b + lx];
            uint32_t a2 = arow0[k2b + lx + 4];
            uint32_t a3 = arow1[k2b + lx + 4];
            #pragma unroll
            for (int nt = 0; nt < NT; nt++) {
                uint32_t b0 = brow[nt*8*BS2 + k2b + lx];
                uint32_t b1v = brow[nt*8*BS2 + k2b + lx + 4];
                mma_f16(C[nt], a0, a1, a2, a3, b0, b1v);
            }
        }
    }
    __syncthreads();   // all warps done reading Apk before staging overwrites it

    // ---- stage C to smem (reuse A region): Cs[j][d] stride CSTR ----
    float* Cs = sm;
    {
        int ly = lane >> 2, lx = lane & 3;
        int jw = wid * 16;
        #pragma unroll
        for (int nt = 0; nt < NT; nt++) {
            int col = 8*nt + 2*lx;
            *(float2*)(Cs + (jw + ly    )*CSTR + col) = make_float2(C[nt][0], C[nt][1]);
            *(float2*)(Cs + (jw + ly + 8)*CSTR + col) = make_float2(C[nt][2], C[nt][3]);
        }
    }
    __syncthreads();

    // ---- epilogue: residual + bn2 + relu (local), conv3 partials P0/P1 ----
    {
        int jrow = tid & 127, dhalf = tid >> 7;
        const float* kcol = g_K1T + (size_t)b*DD*SS + j0 + jrow;
        float p0 = 0.f, p1 = 0.f;
        #pragma unroll 5
        for (int d = dhalf*50; d < dhalf*50 + 50; d++) {
            float t = Cs[jrow*CSTR + d] + Fb[d] + kcol[(size_t)d*SS];
            float val = fmaxf(fmaf(A2s[d], t, C2s[d]), 0.f);
            p0 = fmaf(W30[d], val, p0);
            p1 = fmaf(W31[d], val, p1);
        }
        // reduce the two d-halves via smem (B region is free now)
        float* s0 = (float*)Bpk;
        float* s1 = s0 + 256;
        s0[tid] = p0; s1[tid] = p1;
        __syncthreads();
        if (tid < 128) {
            g_P0[(size_t)(b*SS + i)*SS + j0 + tid] = s0[tid] + s0[tid + 128];
        } else {
            int j = tid - 128;
            g_P1[(size_t)(b*SS + i)*SS + j0 + j] = s1[j] + s1[j + 128];
        }
    }
}

// ============================================================
// Kernel 3: logits from P0/P1 + softmax(j) + attn@v. One block per (b, i).
// Output: [ out (8*254*64) | attn (8*254*256) ]
// ============================================================
__global__ void attn_kernel(const float* __restrict__ b3, const float* __restrict__ v,
                            float* __restrict__ out) {
    int i = blockIdx.x, b = blockIdx.y;
    int tid = threadIdx.x;   // = j
    __shared__ float red[256];
    __shared__ float attn_s[256];

    float logit = (b3[0] + g_P0[(size_t)(b*SS + i)*SS + tid]
                         + g_P1[(size_t)(b*SS + i + 1)*SS + tid]) * TEMP_INV;

    red[tid] = logit; __syncthreads();
    for (int s = 128; s > 0; s >>= 1) { if (tid < s) red[tid] = fmaxf(red[tid], red[tid+s]); __syncthreads(); }
    float mx = red[0]; __syncthreads();
    float p = expf(logit - mx);
    red[tid] = p; __syncthreads();
    for (int s = 128; s > 0; s >>= 1) { if (tid < s) red[tid] += red[tid+s]; __syncthreads(); }
    float inv = 1.f / red[0]; __syncthreads();

    float a = p * inv;
    attn_s[tid] = a;
    out[(size_t)BB*SO*DIMQ + (size_t)(b*SO + i)*SS + tid] = a;
    __syncthreads();

    int t = tid & 63, g = tid >> 6;
    const float* vb = v + (size_t)b*SS*DIMQ + t;
    float acc = 0.f;
    #pragma unroll 4
    for (int j = g*64; j < g*64 + 64; j++) acc += attn_s[j] * vb[(size_t)j*DIMQ];
    red[tid] = acc; __syncthreads();
    if (g == 0)
        out[(size_t)(b*SO + i)*DIMQ + t] = red[t] + red[64+t] + red[128+t] + red[192+t];
}

// ============================================================
extern "C" void kernel_launch(void* const* d_in, const int* in_sizes, int n_in,
                              void* d_out, int out_size) {
    const float* q    = (const float*)d_in[0];
    const float* k    = (const float*)d_in[1];
    const float* v    = (const float*)d_in[2];
    const float* W1   = (const float*)d_in[3];
    const float* b1   = (const float*)d_in[4];
    const float* g1   = (const float*)d_in[5];
    const float* be1  = (const float*)d_in[6];
    const float* m1   = (const float*)d_in[7];
    const float* var1 = (const float*)d_in[8];
    const float* W2   = (const float*)d_in[9];
    const float* b2   = (const float*)d_in[10];
    const float* g2   = (const float*)d_in[11];
    const float* be2  = (const float*)d_in[12];
    const float* m2   = (const float*)d_in[13];
    const float* var2 = (const float*)d_in[14];
    const float* W3   = (const float*)d_in[15];
    const float* b3   = (const float*)d_in[16];
    float* out = (float*)d_out;

    cudaFuncSetAttribute(gemm2_mma, cudaFuncAttributeMaxDynamicSharedMemorySize,
                         SM_WORDS * (int)sizeof(float));

    params_kernel<<<1, 256>>>(W2, b1, b2, g1, be1, m1, var1, g2, be2, m2, var2);
    prep_kernel  <<<dim3((SS*DD + 255)/256, BB, 2), 256>>>(q, k, W1);
    gemm2_mma    <<<dim3(2, SA, BB), 256, SM_WORDS*sizeof(float)>>>(b1, W3);
    attn_kernel  <<<dim3(SO, BB), 256>>>(b3, v, out);
}

// round 11
// speedup vs baseline: 3.7676x; 1.0002x over previous
#include <cuda_runtime.h>
#include <cuda_fp16.h>
#include <cstdint>

// Problem constants
#define BB    8
#define SS    256
#define DIMQ  64
#define DD    100
#define SA    255   // rows of a2
#define SO    254   // output rows
#define TEMP_INV 0.1f
#define EPSV  1e-5f

// GEMM tiling per (b, i, jtile): D[j=128, d=104] = A[j,k] * B[d,k], K padded 200->224 (int8 k32)
#define NPAD  104
#define KK    200
#define NT    13      // 104/8 n-tiles
#define KS32  7       // 224/32 k-steps
#define KW    56      // data words per row (224 bytes / 4)
#define RSTR  60      // smem row stride in u32 words; 60%32=28 -> conflict-free frag loads
#define CSTR  106     // even -> 8B-aligned float2 staging rows; fits under 13920 words

// Scratch (device globals: no allocation allowed)
__device__ float g_Q1[BB*SS*DD];            // [b][i][d]
__device__ float g_K1T[BB*DD*SS];           // [b][c][j]
__device__ float g_P0[BB*SS*SS];            // conv3 partial, h=0 tap
__device__ float g_P1[BB*SS*SS];            // conv3 partial, h=1 tap
__device__ uint32_t g_Bq[NPAD*KW];          // W2 quantized s8, packed words [d][k/4]
__device__ float g_Ud[NPAD];                // per-d B dequant scales
__device__ unsigned g_K1mxE[BB*DD];         // encoded per-(b,c) max of K1
__device__ unsigned g_K1mnE[BB*DD];         // encoded per-(b,c) min of K1
__device__ float g_A1f[DD], g_C1f[DD], g_A2f[DD], g_C2f[DD], g_b12[DD];

// ---------------- helpers ----------------
// Monotone float <-> unsigned encoding (for atomicMax/Min over signed floats)
__device__ __forceinline__ unsigned fenc(float f) {
    unsigned u = __float_as_uint(f);
    return (u & 0x80000000u) ? ~u : (u | 0x80000000u);
}
__device__ __forceinline__ float fdec(unsigned u) {
    unsigned v = (u & 0x80000000u) ? (u & 0x7fffffffu) : ~u;
    return __uint_as_float(v);
}
__device__ __forceinline__ void mma_u8s8(int* c, uint32_t a0, uint32_t a1, uint32_t a2,
                                         uint32_t a3, uint32_t b0, uint32_t b1) {
    asm volatile(
        "mma.sync.aligned.m16n8k32.row.col.s32.u8.s8.s32 "
        "{%0,%1,%2,%3}, {%4,%5,%6,%7}, {%8,%9}, {%0,%1,%2,%3};"
        : "+r"(c[0]), "+r"(c[1]), "+r"(c[2]), "+r"(c[3])
        : "r"(a0), "r"(a1), "r"(a2), "r"(a3), "r"(b0), "r"(b1));
}

// ============================================================
// Kernel 0: params — bn folds, per-d W2 int8 quantization, K1-extreme init
// ============================================================
__global__ void params_kernel(const float* __restrict__ W2,
                              const float* __restrict__ b1, const float* __restrict__ b2,
                              const float* __restrict__ g1, const float* __restrict__ be1,
                              const float* __restrict__ m1, const float* __restrict__ var1,
                              const float* __restrict__ g2, const float* __restrict__ be2,
                              const float* __restrict__ m2, const float* __restrict__ var2) {
    int tid = threadIdx.x;
    if (tid < DD) {
        float A1 = g1[tid] * rsqrtf(var1[tid] + EPSV);
        g_A1f[tid] = A1; g_C1f[tid] = be1[tid] - A1 * m1[tid];
        float A2 = g2[tid] * rsqrtf(var2[tid] + EPSV);
        g_A2f[tid] = A2; g_C2f[tid] = be2[tid] - A2 * m2[tid];
        g_b12[tid] = b1[tid] + b2[tid];
    }
    // init K1 extreme encodings (params runs before prep)
    for (int t = tid; t < BB*DD; t += blockDim.x) {
        g_K1mxE[t] = 0u;            // below every encoded float
        g_K1mnE[t] = 0xffffffffu;   // above every encoded float
    }
    // per-d int8 quantization of W2 (rows d>=DD are zero-padded)
    if (tid < NPAD) {
        int d = tid;
        float mx = 0.f;
        if (d < DD)
            for (int k = 0; k < KK; k++) mx = fmaxf(mx, fabsf(W2[d*KK + k]));
        float u = mx / 127.f;
        g_Ud[d] = u;
        float inv = (mx > 0.f) ? 127.f / mx : 0.f;
        for (int w = 0; w < KW; w++) {
            uint32_t pk = 0;
            #pragma unroll
            for (int bpos = 0; bpos < 4; bpos++) {
                int k = 4*w + bpos;
                int q = 0;
                if (d < DD && k < KK) {
                    q = __float2int_rn(W2[d*KK + k] * inv);
                    q = max(-127, min(127, q));
                }
                pk |= ((uint32_t)(q & 0xff)) << (8*bpos);
            }
            g_Bq[d*KW + w] = pk;
        }
    }
}

// ============================================================
// Kernel 1: Q1[b][i][d], K1T[b][c][j]  (conv1 separates) + K1 extremes
// ============================================================
__global__ void prep_kernel(const float* __restrict__ q, const float* __restrict__ k,
                            const float* __restrict__ W1) {
    int b = blockIdx.y;
    int task = blockIdx.x * blockDim.x + threadIdx.x;
    if (blockIdx.z == 0) {
        if (task >= SA*DD) return;
        int i = task / DD, d = task % DD;
        const float* w  = W1 + d*256;
        const float* q0 = q + (b*SS + i)*DIMQ;
        float s = 0.f;
        #pragma unroll 8
        for (int t = 0; t < DIMQ; t++)
            s += q0[t]*w[2*t] + q0[DIMQ + t]*w[2*t+1];
        g_Q1[(b*SS + i)*DD + d] = s;
    } else {
        if (task >= SS*DD) return;
        int j = task / DD, d = task % DD;
        const float* w  = W1 + d*256 + 128;
        const float* k0 = k + (b*SS + j)*DIMQ;
        float s = 0.f;
        #pragma unroll 8
        for (int t = 0; t < DIMQ; t++)
            s += k0[t]*(w[2*t] + w[2*t+1]);
        g_K1T[(b*DD + d)*SS + j] = s;
        unsigned e = fenc(s);
        atomicMax(&g_K1mxE[b*DD + d], e);
        atomicMin(&g_K1mnE[b*DD + d], e);
    }
}

// ============================================================
// Kernel 2: int8 mma.sync GEMM (m16n8k32 u8.s8.s32) + fused epilogue.
// One CTA per (jtile, i, b): 256 threads = 8 warps, warp tile 16j x 104d.
//  A[128j][224k] u8 generated+quantized on the fly (per-CTA analytic scale)
//  B[104d][224k] s8 copied from pre-quantized g_Bq
//  Epilogue: dequant -> residual -> bn2 -> relu (local) -> conv3 partials P0/P1
// ============================================================
#define W_AQ   0                     // u32 Aq[128][RSTR] = 7680 words
#define W_BQ   7680                  // u32 Bq[104][RSTR] = 6240 words
#define W_PAR  13920                 // 10 param arrays x NPAD
#define W_RED  (W_PAR + 10*NPAD)     // 14960: reduce buffers + scalars
#define SM_WORDS (W_RED + 516)       // 15476 words = 61904 B  (x2 CTAs = 124KB)

__global__ __launch_bounds__(256, 2)
void gemm2_mma(const float* __restrict__ b1, const float* __restrict__ W3) {
    extern __shared__ float sm[];
    uint32_t* Aq = (uint32_t*)sm + W_AQ;
    uint32_t* Bs = (uint32_t*)sm + W_BQ;
    float* Eb0 = sm + W_PAR;
    float* Eb1 = Eb0 + NPAD;
    float* A1s = Eb0 + 2*NPAD;
    float* A1z = Eb0 + 3*NPAD;
    float* Fb  = Eb0 + 4*NPAD;
    float* A2s = Eb0 + 5*NPAD;
    float* C2s = Eb0 + 6*NPAD;
    float* W30 = Eb0 + 7*NPAD;
    float* W31 = Eb0 + 8*NPAD;
    float* SUd = Eb0 + 9*NPAD;
    float* red0 = sm + W_RED;        // 256
    float* red1 = red0 + 256;        // 256
    int*   smaxi = (int*)(red0 + 512);

    int tid = threadIdx.x, wid = tid >> 5, lane = tid & 31;
    int j0 = blockIdx.x * 128, i = blockIdx.y, b = blockIdx.z;

    if (tid == 0) *smaxi = 0;

    // ---- B: copy pre-quantized s8 image (L2-hot) ----
    for (int t = tid; t < NPAD*KW; t += 256) {
        int d = t / KW, w = t % KW;
        Bs[d*RSTR + w] = g_Bq[t];
    }
    // ---- per-CTA folded params + analytic tile-max candidate ----
    if (tid < NPAD) SUd[tid] = g_Ud[tid];
    if (tid < DD) {
        float A1 = g_A1f[tid], C1 = g_C1f[tid];
        float bb = b1[tid];
        float e1 = fmaf(A1, g_Q1[(b*SS + i)*DD + tid] + bb, C1);
        float e0 = (i > 0) ? fmaf(A1, g_Q1[(b*SS + i - 1)*DD + tid] + bb, C1) : C1;
        float a1z = (i > 0) ? A1 : 0.f;
        Eb1[tid] = e1; Eb0[tid] = e0;
        A1s[tid] = A1; A1z[tid] = a1z;
        Fb[tid]  = g_b12[tid] + g_Q1[(b*SS + i)*DD + tid];
        A2s[tid] = g_A2f[tid];
        C2s[tid] = g_C2f[tid];
        W30[tid] = W3[2*tid];
        W31[tid] = W3[2*tid + 1];
        // tile upper bound from per-(b,c) K1 extremes (covers both signs of A1)
        float kx = fdec(g_K1mxE[b*DD + tid]);
        float kn = fdec(g_K1mnE[b*DD + tid]);
        float m = fmaxf(fmaxf(fmaxf(fmaf(a1z, kx, e0), fmaf(a1z, kn, e0)),
                              fmaxf(fmaf(A1,  kx, e1), fmaf(A1,  kn, e1))), 0.f);
        atomicMax(smaxi, __float_as_int(m));   // m >= 0: int compare valid
    }
    __syncthreads();

    float amax = __int_as_float(*smaxi);
    float s_a   = amax / 255.f;
    float inv_s = (amax > 0.f) ? 255.f / amax : 0.f;

    // ---- A generation: r1 on the fly -> u8 quantize -> packed words ----
    {
        int j = tid & 127, half = tid >> 7;
        const float* kcol = g_K1T + (size_t)b*DD*SS + j0 + j;
        uint32_t* arow = Aq + j*RSTR;
        #pragma unroll 5
        for (int w = half*25; w < half*25 + 25; w++) {
            int c0 = 2*w, c1 = 2*w + 1;
            float kv0 = kcol[(size_t)c0*SS];
            float kv1 = kcol[(size_t)c1*SS];
            float v00 = fmaxf(fmaf(A1z[c0], kv0, Eb0[c0]), 0.f);
            float v01 = fmaxf(fmaf(A1s[c0], kv0, Eb1[c0]), 0.f);
            float v10 = fmaxf(fmaf(A1z[c1], kv1, Eb0[c1]), 0.f);
            float v11 = fmaxf(fmaf(A1s[c1], kv1, Eb1[c1]), 0.f);
            uint32_t q0 = min(__float2uint_rn(v00 * inv_s), 255u);
            uint32_t q1 = min(__float2uint_rn(v01 * inv_s), 255u);
            uint32_t q2 = min(__float2uint_rn(v10 * inv_s), 255u);
            uint32_t q3 = min(__float2uint_rn(v11 * inv_s), 255u);
            arow[w] = q0 | (q1 << 8) | (q2 << 16) | (q3 << 24);
        }
        // zero K-pad words 50..55
        arow[50 + half*3]     = 0u;
        arow[50 + half*3 + 1] = 0u;
        arow[50 + half*3 + 2] = 0u;
    }
    __syncthreads();

    // ---- MMA mainloop: warp tile 16j x 104d, m16n8k32 u8.s8 ----
    int C[NT][4];
    #pragma unroll
    for (int nt = 0; nt < NT; nt++)
        #pragma unroll
        for (int r = 0; r < 4; r++) C[nt][r] = 0;

    {
        int ly = lane >> 2, lx = lane & 3;
        int jw = wid * 16;
        const uint32_t* arow0 = Aq + (jw + ly)*RSTR;
        const uint32_t* arow1 = Aq + (jw + ly + 8)*RSTR;
        const uint32_t* brow  = Bs + ly*RSTR;
        #pragma unroll
        for (int ks = 0; ks < KS32; ks++) {
            int kw = 8*ks;
            uint32_t a0 = arow0[kw + lx];
            uint32_t a1 = arow1[kw + lx];
            uint32_t a2 = arow0[kw + lx + 4];
            uint32_t a3 = arow1[kw + lx + 4];
            #pragma unroll
            for (int nt = 0; nt < NT; nt++) {
                uint32_t b0 = brow[nt*8*RSTR + kw + lx];
                uint32_t b1v = brow[nt*8*RSTR + kw + lx + 4];
                mma_u8s8(C[nt], a0, a1, a2, a3, b0, b1v);
            }
        }
    }
    __syncthreads();   // all warps done with Aq/Bs before staging overwrites

    // ---- dequant + stage to smem: Cs[j][d] stride CSTR (reuses Aq/Bs region) ----
    float* Cs = sm;
    {
        int ly = lane >> 2, lx = lane & 3;
        int jw = wid * 16;
        #pragma unroll
        for (int nt = 0; nt < NT; nt++) {
            int col = 8*nt + 2*lx;
            float u0 = s_a * SUd[col], u1 = s_a * SUd[col + 1];
            *(float2*)(Cs + (jw + ly    )*CSTR + col) =
                make_float2((float)C[nt][0] * u0, (float)C[nt][1] * u1);
            *(float2*)(Cs + (jw + ly + 8)*CSTR + col) =
                make_float2((float)C[nt][2] * u0, (float)C[nt][3] * u1);
        }
    }
    __syncthreads();

    // ---- epilogue: residual + bn2 + relu (local), conv3 partials P0/P1 ----
    {
        int jrow = tid & 127, dhalf = tid >> 7;
        const float* kcol = g_K1T + (size_t)b*DD*SS + j0 + jrow;
        float p0 = 0.f, p1 = 0.f;
        #pragma unroll 5
        for (int d = dhalf*50; d < dhalf*50 + 50; d++) {
            float t = Cs[jrow*CSTR + d] + Fb[d] + kcol[(size_t)d*SS];
            float val = fmaxf(fmaf(A2s[d], t, C2s[d]), 0.f);
            p0 = fmaf(W30[d], val, p0);
            p1 = fmaf(W31[d], val, p1);
        }
        red0[tid] = p0; red1[tid] = p1;
        __syncthreads();
        if (tid < 128) {
            g_P0[(size_t)(b*SS + i)*SS + j0 + tid] = red0[tid] + red0[tid + 128];
        } else {
            int j = tid - 128;
            g_P1[(size_t)(b*SS + i)*SS + j0 + j] = red1[j] + red1[j + 128];
        }
    }
}

// ============================================================
// Kernel 3: logits from P0/P1 + softmax(j) + attn@v. One block per (b, i).
// Output: [ out (8*254*64) | attn (8*254*256) ]
// ============================================================
__global__ void attn_kernel(const float* __restrict__ b3, const float* __restrict__ v,
                            float* __restrict__ out) {
    int i = blockIdx.x, b = blockIdx.y;
    int tid = threadIdx.x;   // = j
    __shared__ float red[256];
    __shared__ float attn_s[256];

    float logit = (b3[0] + g_P0[(size_t)(b*SS + i)*SS + tid]
                         + g_P1[(size_t)(b*SS + i + 1)*SS + tid]) * TEMP_INV;

    red[tid] = logit; __syncthreads();
    for (int s = 128; s > 0; s >>= 1) { if (tid < s) red[tid] = fmaxf(red[tid], red[tid+s]); __syncthreads(); }
    float mx = red[0]; __syncthreads();
    float p = expf(logit - mx);
    red[tid] = p; __syncthreads();
    for (int s = 128; s > 0; s >>= 1) { if (tid < s) red[tid] += red[tid+s]; __syncthreads(); }
    float inv = 1.f / red[0]; __syncthreads();

    float a = p * inv;
    attn_s[tid] = a;
    out[(size_t)BB*SO*DIMQ + (size_t)(b*SO + i)*SS + tid] = a;
    __syncthreads();

    int t = tid & 63, g = tid >> 6;
    const float* vb = v + (size_t)b*SS*DIMQ + t;
    float acc = 0.f;
    #pragma unroll 4
    for (int j = g*64; j < g*64 + 64; j++) acc += attn_s[j] * vb[(size_t)j*DIMQ];
    red[tid] = acc; __syncthreads();
    if (g == 0)
        out[(size_t)(b*SO + i)*DIMQ + t] = red[t] + red[64+t] + red[128+t] + red[192+t];
}

// ============================================================
extern "C" void kernel_launch(void* const* d_in, const int* in_sizes, int n_in,
                              void* d_out, int out_size) {
    const float* q    = (const float*)d_in[0];
    const float* k    = (const float*)d_in[1];
    const float* v    = (const float*)d_in[2];
    const float* W1   = (const float*)d_in[3];
    const float* b1   = (const float*)d_in[4];
    const float* g1   = (const float*)d_in[5];
    const float* be1  = (const float*)d_in[6];
    const float* m1   = (const float*)d_in[7];
    const float* var1 = (const float*)d_in[8];
    const float* W2   = (const float*)d_in[9];
    const float* b2   = (const float*)d_in[10];
    const float* g2   = (const float*)d_in[11];
    const float* be2  = (const float*)d_in[12];
    const float* m2   = (const float*)d_in[13];
    const float* var2 = (const float*)d_in[14];
    const float* W3   = (const float*)d_in[15];
    const float* b3   = (const float*)d_in[16];
    float* out = (float*)d_out;

    cudaFuncSetAttribute(gemm2_mma, cudaFuncAttributeMaxDynamicSharedMemorySize,
                         SM_WORDS * (int)sizeof(float));

    params_kernel<<<1, 256>>>(W2, b1, b2, g1, be1, m1, var1, g2, be2, m2, var2);
    prep_kernel  <<<dim3((SS*DD + 255)/256, BB, 2), 256>>>(q, k, W1);
    gemm2_mma    <<<dim3(2, SA, BB), 256, SM_WORDS*sizeof(float)>>>(b1, W3);
    attn_kernel  <<<dim3(SO, BB), 256>>>(b3, v, out);
}

// round 12
// speedup vs baseline: 5.6607x; 1.5025x over previous
#include <cuda_runtime.h>
#include <cuda_fp16.h>
#include <cstdint>

// Problem constants
#define BB    8
#define SS    256
#define DIMQ  64
#define DD    100
#define SA    255   // rows of a2
#define SO    254   // output rows
#define TEMP_INV 0.1f
#define EPSV  1e-5f

// GEMM tiling per (b, i, jtile): D[j=128, d=104] = A[j,k] * B[d,k], K padded 200->224 (int8 k32)
#define NPAD  104
#define KK    200
#define NT    13      // 104/8 n-tiles
#define KS32  7       // 224/32 k-steps
#define KW    56      // data words per row (224 bytes / 4)
#define RSTR  60      // smem row stride in u32 words; 60%32=28 -> conflict-free frag loads
#define CSTR  106     // even -> 8B-aligned float2 staging rows; fits under 13920 words

// Scratch (device globals: no allocation allowed)
__device__ float g_Q1[BB*SS*DD];            // [b][i][d]
__device__ float g_K1T[BB*DD*SS];           // [b][c][j]
__device__ float g_P0[BB*SS*SS];            // conv3 partial, h=0 tap
__device__ float g_P1[BB*SS*SS];            // conv3 partial, h=1 tap
__device__ uint32_t g_Bq[NPAD*KW];          // W2 quantized s8, packed words [d][k/4]
__device__ float g_Ud[NPAD];                // per-d B dequant scales
__device__ unsigned g_K1mxE[BB*DD];         // encoded per-(b,c) max of K1
__device__ unsigned g_K1mnE[BB*DD];         // encoded per-(b,c) min of K1
__device__ float g_WqT[2*DIMQ*DD];          // W1 q-branch transposed: [t2][d] (t2=0..127)
__device__ float g_WkT[DIMQ*DD];            // W1 k-branch taps summed, transposed: [t][d]
__device__ float g_A1f[DD], g_C1f[DD], g_A2f[DD], g_C2f[DD], g_b12[DD];

// ---------------- helpers ----------------
// Monotone float <-> unsigned encoding (for atomicMax/Min over signed floats)
__device__ __forceinline__ unsigned fenc(float f) {
    unsigned u = __float_as_uint(f);
    return (u & 0x80000000u) ? ~u : (u | 0x80000000u);
}
__device__ __forceinline__ float fdec(unsigned u) {
    unsigned v = (u & 0x80000000u) ? (u & 0x7fffffffu) : ~u;
    return __uint_as_float(v);
}
__device__ __forceinline__ void mma_u8s8(int* c, uint32_t a0, uint32_t a1, uint32_t a2,
                                         uint32_t a3, uint32_t b0, uint32_t b1) {
    asm volatile(
        "mma.sync.aligned.m16n8k32.row.col.s32.u8.s8.s32 "
        "{%0,%1,%2,%3}, {%4,%5,%6,%7}, {%8,%9}, {%0,%1,%2,%3};"
        : "+r"(c[0]), "+r"(c[1]), "+r"(c[2]), "+r"(c[3])
        : "r"(a0), "r"(a1), "r"(a2), "r"(a3), "r"(b0), "r"(b1));
}

// ============================================================
// Kernel 0: params — bn folds, W2 int8 quant, W1 transposes, K1-extreme init
// ============================================================
__global__ void params_kernel(const float* __restrict__ W1, const float* __restrict__ W2,
                              const float* __restrict__ b1, const float* __restrict__ b2,
                              const float* __restrict__ g1, const float* __restrict__ be1,
                              const float* __restrict__ m1, const float* __restrict__ var1,
                              const float* __restrict__ g2, const float* __restrict__ be2,
                              const float* __restrict__ m2, const float* __restrict__ var2) {
    int tid = threadIdx.x;
    if (tid < DD) {
        float A1 = g1[tid] * rsqrtf(var1[tid] + EPSV);
        g_A1f[tid] = A1; g_C1f[tid] = be1[tid] - A1 * m1[tid];
        float A2 = g2[tid] * rsqrtf(var2[tid] + EPSV);
        g_A2f[tid] = A2; g_C2f[tid] = be2[tid] - A2 * m2[tid];
        g_b12[tid] = b1[tid] + b2[tid];
    }
    // init K1 extreme encodings (params runs before prep)
    for (int t = tid; t < BB*DD; t += blockDim.x) {
        g_K1mxE[t] = 0u;            // below every encoded float
        g_K1mnE[t] = 0xffffffffu;   // above every encoded float
    }
    // W1 transposes for coalesced prep loads.
    // Q1[b,i,d] = sum_t q[b,i,t]*W1[d,t,0] + q[b,i+1,t]*W1[d,t,1]
    //   g_WqT rows 0..63  = W1[d, t, 0];  rows 64..127 = W1[d, t, 1]
    for (int t = tid; t < 2*DIMQ*DD; t += blockDim.x) {
        int r = t / DD, d = t % DD;
        g_WqT[t] = (r < DIMQ) ? W1[d*256 + r*2] : W1[d*256 + (r - DIMQ)*2 + 1];
    }
    // K1[b,j,d] = sum_t k[b,j,t]*(W1[d,64+t,0]+W1[d,64+t,1])
    for (int t = tid; t < DIMQ*DD; t += blockDim.x) {
        int r = t / DD, d = t % DD;
        g_WkT[t] = W1[d*256 + 128 + r*2] + W1[d*256 + 128 + r*2 + 1];
    }
    // per-d int8 quantization of W2 (rows d>=DD are zero-padded)
    if (tid < NPAD) {
        int d = tid;
        float mx = 0.f;
        if (d < DD)
            for (int k = 0; k < KK; k++) mx = fmaxf(mx, fabsf(W2[d*KK + k]));
        float u = mx / 127.f;
        g_Ud[d] = u;
        float inv = (mx > 0.f) ? 127.f / mx : 0.f;
        for (int w = 0; w < KW; w++) {
            uint32_t pk = 0;
            #pragma unroll
            for (int bpos = 0; bpos < 4; bpos++) {
                int k = 4*w + bpos;
                int q = 0;
                if (d < DD && k < KK) {
                    q = __float2int_rn(W2[d*KK + k] * inv);
                    q = max(-127, min(127, q));
                }
                pk |= ((uint32_t)(q & 0xff)) << (8*bpos);
            }
            g_Bq[d*KW + w] = pk;
        }
    }
}

// ============================================================
// Kernel 1: Q1[b][i][d], K1T[b][c][j] via transposed weights (coalesced on d)
// ============================================================
__global__ void prep_kernel(const float* __restrict__ q, const float* __restrict__ k) {
    int b = blockIdx.y;
    int task = blockIdx.x * blockDim.x + threadIdx.x;
    if (blockIdx.z == 0) {
        if (task >= SA*DD) return;
        int i = task / DD, d = task % DD;
        const float* q0 = q + (b*SS + i)*DIMQ;   // rows i and i+1 contiguous
        float s = 0.f;
        #pragma unroll 8
        for (int t = 0; t < DIMQ; t++)
            s += q0[t]*g_WqT[t*DD + d] + q0[DIMQ + t]*g_WqT[(DIMQ + t)*DD + d];
        g_Q1[(b*SS + i)*DD + d] = s;
    } else {
        if (task >= SS*DD) return;
        int j = task / DD, d = task % DD;
        const float* k0 = k + (b*SS + j)*DIMQ;
        float s = 0.f;
        #pragma unroll 8
        for (int t = 0; t < DIMQ; t++)
            s += k0[t]*g_WkT[t*DD + d];
        g_K1T[(b*DD + d)*SS + j] = s;
        unsigned e = fenc(s);
        atomicMax(&g_K1mxE[b*DD + d], e);
        atomicMin(&g_K1mnE[b*DD + d], e);
    }
}

// ============================================================
// Kernel 2: int8 mma.sync GEMM (m16n8k32 u8.s8.s32) + fused epilogue.
// One CTA per (jtile, i, b): 256 threads = 8 warps, warp tile 16j x 104d.
//  A[128j][224k] u8 generated+quantized on the fly (per-CTA analytic scale)
//  B[104d][224k] s8 copied from pre-quantized g_Bq
//  Epilogue: dequant -> residual -> bn2 -> relu (local) -> conv3 partials P0/P1
// ============================================================
#define W_AQ   0                     // u32 Aq[128][RSTR] = 7680 words
#define W_BQ   7680                  // u32 Bq[104][RSTR] = 6240 words
#define W_PAR  13920                 // 10 param arrays x NPAD
#define W_RED  (W_PAR + 10*NPAD)     // 14960: reduce buffers + scalars
#define SM_WORDS (W_RED + 516)       // 15476 words = 61904 B  (x2 CTAs = 124KB)

__global__ __launch_bounds__(256, 2)
void gemm2_mma(const float* __restrict__ b1, const float* __restrict__ W3) {
    extern __shared__ float sm[];
    uint32_t* Aq = (uint32_t*)sm + W_AQ;
    uint32_t* Bs = (uint32_t*)sm + W_BQ;
    float* Eb0 = sm + W_PAR;
    float* Eb1 = Eb0 + NPAD;
    float* A1s = Eb0 + 2*NPAD;
    float* A1z = Eb0 + 3*NPAD;
    float* Fb  = Eb0 + 4*NPAD;
    float* A2s = Eb0 + 5*NPAD;
    float* C2s = Eb0 + 6*NPAD;
    float* W30 = Eb0 + 7*NPAD;
    float* W31 = Eb0 + 8*NPAD;
    float* SUd = Eb0 + 9*NPAD;
    float* red0 = sm + W_RED;        // 256
    float* red1 = red0 + 256;        // 256
    int*   smaxi = (int*)(red0 + 512);

    int tid = threadIdx.x, wid = tid >> 5, lane = tid & 31;
    int j0 = blockIdx.x * 128, i = blockIdx.y, b = blockIdx.z;

    if (tid == 0) *smaxi = 0;

    // ---- B: copy pre-quantized s8 image (L2-hot) ----
    for (int t = tid; t < NPAD*KW; t += 256) {
        int d = t / KW, w = t % KW;
        Bs[d*RSTR + w] = g_Bq[t];
    }
    // ---- per-CTA folded params + analytic tile-max candidate ----
    if (tid < NPAD) SUd[tid] = g_Ud[tid];
    if (tid < DD) {
        float A1 = g_A1f[tid], C1 = g_C1f[tid];
        float bb = b1[tid];
        float e1 = fmaf(A1, g_Q1[(b*SS + i)*DD + tid] + bb, C1);
        float e0 = (i > 0) ? fmaf(A1, g_Q1[(b*SS + i - 1)*DD + tid] + bb, C1) : C1;
        float a1z = (i > 0) ? A1 : 0.f;
        Eb1[tid] = e1; Eb0[tid] = e0;
        A1s[tid] = A1; A1z[tid] = a1z;
        Fb[tid]  = g_b12[tid] + g_Q1[(b*SS + i)*DD + tid];
        A2s[tid] = g_A2f[tid];
        C2s[tid] = g_C2f[tid];
        W30[tid] = W3[2*tid];
        W31[tid] = W3[2*tid + 1];
        // tile upper bound from per-(b,c) K1 extremes (covers both signs of A1)
        float kx = fdec(g_K1mxE[b*DD + tid]);
        float kn = fdec(g_K1mnE[b*DD + tid]);
        float m = fmaxf(fmaxf(fmaxf(fmaf(a1z, kx, e0), fmaf(a1z, kn, e0)),
                              fmaxf(fmaf(A1,  kx, e1), fmaf(A1,  kn, e1))), 0.f);
        atomicMax(smaxi, __float_as_int(m));   // m >= 0: int compare valid
    }
    __syncthreads();

    float amax = __int_as_float(*smaxi);
    float s_a   = amax / 255.f;
    float inv_s = (amax > 0.f) ? 255.f / amax : 0.f;

    // ---- A generation: r1 on the fly -> u8 quantize -> packed words ----
    {
        int j = tid & 127, half = tid >> 7;
        const float* kcol = g_K1T + (size_t)b*DD*SS + j0 + j;
        uint32_t* arow = Aq + j*RSTR;
        #pragma unroll 5
        for (int w = half*25; w < half*25 + 25; w++) {
            int c0 = 2*w, c1 = 2*w + 1;
            float kv0 = kcol[(size_t)c0*SS];
            float kv1 = kcol[(size_t)c1*SS];
            float v00 = fmaxf(fmaf(A1z[c0], kv0, Eb0[c0]), 0.f);
            float v01 = fmaxf(fmaf(A1s[c0], kv0, Eb1[c0]), 0.f);
            float v10 = fmaxf(fmaf(A1z[c1], kv1, Eb0[c1]), 0.f);
            float v11 = fmaxf(fmaf(A1s[c1], kv1, Eb1[c1]), 0.f);
            uint32_t q0 = min(__float2uint_rn(v00 * inv_s), 255u);
            uint32_t q1 = min(__float2uint_rn(v01 * inv_s), 255u);
            uint32_t q2 = min(__float2uint_rn(v10 * inv_s), 255u);
            uint32_t q3 = min(__float2uint_rn(v11 * inv_s), 255u);
            arow[w] = q0 | (q1 << 8) | (q2 << 16) | (q3 << 24);
        }
        // zero K-pad words 50..55
        arow[50 + half*3]     = 0u;
        arow[50 + half*3 + 1] = 0u;
        arow[50 + half*3 + 2] = 0u;
    }
    __syncthreads();

    // ---- MMA mainloop: warp tile 16j x 104d, m16n8k32 u8.s8 ----
    int C[NT][4];
    #pragma unroll
    for (int nt = 0; nt < NT; nt++)
        #pragma unroll
        for (int r = 0; r < 4; r++) C[nt][r] = 0;

    {
        int ly = lane >> 2, lx = lane & 3;
        int jw = wid * 16;
        const uint32_t* arow0 = Aq + (jw + ly)*RSTR;
        const uint32_t* arow1 = Aq + (jw + ly + 8)*RSTR;
        const uint32_t* brow  = Bs + ly*RSTR;
        #pragma unroll
        for (int ks = 0; ks < KS32; ks++) {
            int kw = 8*ks;
            uint32_t a0 = arow0[kw + lx];
            uint32_t a1 = arow1[kw + lx];
            uint32_t a2 = arow0[kw + lx + 4];
            uint32_t a3 = arow1[kw + lx + 4];
            #pragma unroll
            for (int nt = 0; nt < NT; nt++) {
                uint32_t b0 = brow[nt*8*RSTR + kw + lx];
                uint32_t b1v = brow[nt*8*RSTR + kw + lx + 4];
                mma_u8s8(C[nt], a0, a1, a2, a3, b0, b1v);
            }
        }
    }
    __syncthreads();   // all warps done with Aq/Bs before staging overwrites

    // ---- dequant + stage to smem: Cs[j][d] stride CSTR (reuses Aq/Bs region) ----
    float* Cs = sm;
    {
        int ly = lane >> 2, lx = lane & 3;
        int jw = wid * 16;
        #pragma unroll
        for (int nt = 0; nt < NT; nt++) {
            int col = 8*nt + 2*lx;
            float u0 = s_a * SUd[col], u1 = s_a * SUd[col + 1];
            *(float2*)(Cs + (jw + ly    )*CSTR + col) =
                make_float2((float)C[nt][0] * u0, (float)C[nt][1] * u1);
            *(float2*)(Cs + (jw + ly + 8)*CSTR + col) =
                make_float2((float)C[nt][2] * u0, (float)C[nt][3] * u1);
        }
    }
    __syncthreads();

    // ---- epilogue: residual + bn2 + relu (local), conv3 partials P0/P1 ----
    {
        int jrow = tid & 127, dhalf = tid >> 7;
        const float* kcol = g_K1T + (size_t)b*DD*SS + j0 + jrow;
        float p0 = 0.f, p1 = 0.f;
        #pragma unroll 5
        for (int d = dhalf*50; d < dhalf*50 + 50; d++) {
            float t = Cs[jrow*CSTR + d] + Fb[d] + kcol[(size_t)d*SS];
            float val = fmaxf(fmaf(A2s[d], t, C2s[d]), 0.f);
            p0 = fmaf(W30[d], val, p0);
            p1 = fmaf(W31[d], val, p1);
        }
        red0[tid] = p0; red1[tid] = p1;
        __syncthreads();
        if (tid < 128) {
            g_P0[(size_t)(b*SS + i)*SS + j0 + tid] = red0[tid] + red0[tid + 128];
        } else {
            int j = tid - 128;
            g_P1[(size_t)(b*SS + i)*SS + j0 + j] = red1[j] + red1[j + 128];
        }
    }
}

// ============================================================
// Kernel 3: logits from P0/P1 + softmax(j) + attn@v. One block per (b, i).
// Output: [ out (8*254*64) | attn (8*254*256) ]
// ============================================================
__global__ void attn_kernel(const float* __restrict__ b3, const float* __restrict__ v,
                            float* __restrict__ out) {
    int i = blockIdx.x, b = blockIdx.y;
    int tid = threadIdx.x;   // = j
    __shared__ float red[256];
    __shared__ float attn_s[256];

    float logit = (b3[0] + g_P0[(size_t)(b*SS + i)*SS + tid]
                         + g_P1[(size_t)(b*SS + i + 1)*SS + tid]) * TEMP_INV;

    red[tid] = logit; __syncthreads();
    for (int s = 128; s > 0; s >>= 1) { if (tid < s) red[tid] = fmaxf(red[tid], red[tid+s]); __syncthreads(); }
    float mx = red[0]; __syncthreads();
    float p = expf(logit - mx);
    red[tid] = p; __syncthreads();
    for (int s = 128; s > 0; s >>= 1) { if (tid < s) red[tid] += red[tid+s]; __syncthreads(); }
    float inv = 1.f / red[0]; __syncthreads();

    float a = p * inv;
    attn_s[tid] = a;
    out[(size_t)BB*SO*DIMQ + (size_t)(b*SO + i)*SS + tid] = a;
    __syncthreads();

    int t = tid & 63, g = tid >> 6;
    const float* vb = v + (size_t)b*SS*DIMQ + t;
    float acc = 0.f;
    #pragma unroll 4
    for (int j = g*64; j < g*64 + 64; j++) acc += attn_s[j] * vb[(size_t)j*DIMQ];
    red[tid] = acc; __syncthreads();
    if (g == 0)
        out[(size_t)(b*SO + i)*DIMQ + t] = red[t] + red[64+t] + red[128+t] + red[192+t];
}

// ============================================================
extern "C" void kernel_launch(void* const* d_in, const int* in_sizes, int n_in,
                              void* d_out, int out_size) {
    const float* q    = (const float*)d_in[0];
    const float* k    = (const float*)d_in[1];
    const float* v    = (const float*)d_in[2];
    const float* W1   = (const float*)d_in[3];
    const float* b1   = (const float*)d_in[4];
    const float* g1   = (const float*)d_in[5];
    const float* be1  = (const float*)d_in[6];
    const float* m1   = (const float*)d_in[7];
    const float* var1 = (const float*)d_in[8];
    const float* W2   = (const float*)d_in[9];
    const float* b2   = (const float*)d_in[10];
    const float* g2   = (const float*)d_in[11];
    const float* be2  = (const float*)d_in[12];
    const float* m2   = (const float*)d_in[13];
    const float* var2 = (const float*)d_in[14];
    const float* W3   = (const float*)d_in[15];
    const float* b3   = (const float*)d_in[16];
    float* out = (float*)d_out;

    cudaFuncSetAttribute(gemm2_mma, cudaFuncAttributeMaxDynamicSharedMemorySize,
                         SM_WORDS * (int)sizeof(float));

    params_kernel<<<1, 256>>>(W1, W2, b1, b2, g1, be1, m1, var1, g2, be2, m2, var2);
    prep_kernel  <<<dim3((SS*DD + 255)/256, BB, 2), 256>>>(q, k);
    gemm2_mma    <<<dim3(2, SA, BB), 256, SM_WORDS*sizeof(float)>>>(b1, W3);
    attn_kernel  <<<dim3(SO, BB), 256>>>(b3, v, out);
}

// round 14
// speedup vs baseline: 6.2211x; 1.0990x over previous
#include <cuda_runtime.h>
#include <cuda_fp16.h>
#include <cstdint>

// Problem constants
#define BB    8
#define SS    256
#define DIMQ  64
#define DD    100
#define SA    255   // rows of a2
#define SO    254   // output rows
#define TEMP_INV 0.1f
#define EPSV  1e-5f

// GEMM tiling per (b, i, jtile): D[j=128, d=104] = A[j,k] * B[d,k], K padded 200->224 (int8 k32)
#define NPAD  104
#define KK    200
#define NT    13      // 104/8 n-tiles
#define KS32  7       // 224/32 k-steps
#define KW    56      // data words per row (224 bytes / 4)
#define RSTR  60      // smem row stride in u32 words; 60%32=28 -> conflict-free frag loads
#define CSTR  106     // even -> 8B-aligned float2 staging rows; fits under 13920 words

// Scratch (device globals: no allocation allowed)
__device__ float g_Q1[BB*SS*DD];            // [b][i][d]
__device__ float g_K1T[BB*DD*SS];           // [b][c][j]
__device__ float g_P0[BB*SS*SS];            // conv3 partial, h=0 tap
__device__ float g_P1[BB*SS*SS];            // conv3 partial, h=1 tap
__device__ uint32_t g_Bq[NPAD*KW];          // W2 quantized s8, packed words [d][k/4]
__device__ float g_Ud[NPAD];                // per-d B dequant scales
__device__ unsigned g_K1mxE[BB*DD];         // encoded per-(b,c) max of K1
__device__ unsigned g_K1mnE[BB*DD];         // encoded per-(b,c) min of K1
__device__ float g_WqT[2*DIMQ*DD];          // W1 q-branch transposed: [t2][d] (t2=0..127)
__device__ float g_WkT[DIMQ*DD];            // W1 k-branch taps summed, transposed: [t][d]
__device__ float g_A1f[DD], g_C1f[DD], g_A2f[DD], g_C2f[DD], g_b12[DD];

// ---------------- helpers ----------------
// Monotone float <-> unsigned encoding (for atomicMax/Min over signed floats)
__device__ __forceinline__ unsigned fenc(float f) {
    unsigned u = __float_as_uint(f);
    return (u & 0x80000000u) ? ~u : (u | 0x80000000u);
}
__device__ __forceinline__ float fdec(unsigned u) {
    unsigned v = (u & 0x80000000u) ? (u & 0x7fffffffu) : ~u;
    return __uint_as_float(v);
}
__device__ __forceinline__ void mma_u8s8(int* c, uint32_t a0, uint32_t a1, uint32_t a2,
                                         uint32_t a3, uint32_t b0, uint32_t b1) {
    asm volatile(
        "mma.sync.aligned.m16n8k32.row.col.s32.u8.s8.s32 "
        "{%0,%1,%2,%3}, {%4,%5,%6,%7}, {%8,%9}, {%0,%1,%2,%3};"
        : "+r"(c[0]), "+r"(c[1]), "+r"(c[2]), "+r"(c[3])
        : "r"(a0), "r"(a1), "r"(a2), "r"(a3), "r"(b0), "r"(b1));
}

// ============================================================
// Kernel 0: params — bn folds, W2 int8 quant, W1 transposes, K1-extreme init
// ============================================================
__global__ void params_kernel(const float* __restrict__ W1, const float* __restrict__ W2,
                              const float* __restrict__ b1, const float* __restrict__ b2,
                              const float* __restrict__ g1, const float* __restrict__ be1,
                              const float* __restrict__ m1, const float* __restrict__ var1,
                              const float* __restrict__ g2, const float* __restrict__ be2,
                              const float* __restrict__ m2, const float* __restrict__ var2) {
    int tid = threadIdx.x;
    if (tid < DD) {
        float A1 = g1[tid] * rsqrtf(var1[tid] + EPSV);
        g_A1f[tid] = A1; g_C1f[tid] = be1[tid] - A1 * m1[tid];
        float A2 = g2[tid] * rsqrtf(var2[tid] + EPSV);
        g_A2f[tid] = A2; g_C2f[tid] = be2[tid] - A2 * m2[tid];
        g_b12[tid] = b1[tid] + b2[tid];
    }
    // init K1 extreme encodings (params runs before prep)
    for (int t = tid; t < BB*DD; t += blockDim.x) {
        g_K1mxE[t] = 0u;            // below every encoded float
        g_K1mnE[t] = 0xffffffffu;   // above every encoded float
    }
    // W1 transposes for coalesced prep loads.
    for (int t = tid; t < 2*DIMQ*DD; t += blockDim.x) {
        int r = t / DD, d = t % DD;
        g_WqT[t] = (r < DIMQ) ? W1[d*256 + r*2] : W1[d*256 + (r - DIMQ)*2 + 1];
    }
    for (int t = tid; t < DIMQ*DD; t += blockDim.x) {
        int r = t / DD, d = t % DD;
        g_WkT[t] = W1[d*256 + 128 + r*2] + W1[d*256 + 128 + r*2 + 1];
    }
    // per-d int8 quantization of W2 (rows d>=DD are zero-padded)
    if (tid < NPAD) {
        int d = tid;
        float mx = 0.f;
        if (d < DD)
            for (int k = 0; k < KK; k++) mx = fmaxf(mx, fabsf(W2[d*KK + k]));
        float u = mx / 127.f;
        g_Ud[d] = u;
        float inv = (mx > 0.f) ? 127.f / mx : 0.f;
        for (int w = 0; w < KW; w++) {
            uint32_t pk = 0;
            #pragma unroll
            for (int bpos = 0; bpos < 4; bpos++) {
                int k = 4*w + bpos;
                int q = 0;
                if (d < DD && k < KK) {
                    q = __float2int_rn(W2[d*KK + k] * inv);
                    q = max(-127, min(127, q));
                }
                pk |= ((uint32_t)(q & 0xff)) << (8*bpos);
            }
            g_Bq[d*KW + w] = pk;
        }
    }
}

// ============================================================
// Kernel 1: Q1[b][i][d], K1T[b][c][j] via transposed weights (coalesced on d)
// ============================================================
__global__ void prep_kernel(const float* __restrict__ q, const float* __restrict__ k) {
    int b = blockIdx.y;
    int task = blockIdx.x * blockDim.x + threadIdx.x;
    if (blockIdx.z == 0) {
        if (task >= SA*DD) return;
        int i = task / DD, d = task % DD;
        const float* q0 = q + (b*SS + i)*DIMQ;   // rows i and i+1 contiguous
        float s = 0.f;
        #pragma unroll 8
        for (int t = 0; t < DIMQ; t++)
            s += q0[t]*g_WqT[t*DD + d] + q0[DIMQ + t]*g_WqT[(DIMQ + t)*DD + d];
        g_Q1[(b*SS + i)*DD + d] = s;
    } else {
        if (task >= SS*DD) return;
        int j = task / DD, d = task % DD;
        const float* k0 = k + (b*SS + j)*DIMQ;
        float s = 0.f;
        #pragma unroll 8
        for (int t = 0; t < DIMQ; t++)
            s += k0[t]*g_WkT[t*DD + d];
        g_K1T[(b*DD + d)*SS + j] = s;
        unsigned e = fenc(s);
        atomicMax(&g_K1mxE[b*DD + d], e);
        atomicMin(&g_K1mnE[b*DD + d], e);
    }
}

// ============================================================
// Kernel 2: int8 mma.sync GEMM (m16n8k32 u8.s8.s32) + fused epilogue.
// One CTA per (jtile, i, b): 256 threads = 8 warps, warp tile 16j x 104d.
// occ=3 CTAs/SM (smem 61.9KB x 3 = 185.7KB; regs capped 85).
// ============================================================
#define W_AQ   0                     // u32 Aq[128][RSTR] = 7680 words
#define W_BQ   7680                  // u32 Bq[104][RSTR] = 6240 words
#define W_PAR  13920                 // 10 param arrays x NPAD
#define W_RED  (W_PAR + 10*NPAD)     // 14960: reduce buffers + scalars
#define SM_WORDS (W_RED + 516)       // 15476 words = 61904 B

__global__ __launch_bounds__(256, 3)
void gemm2_mma(const float* __restrict__ b1, const float* __restrict__ W3) {
    extern __shared__ float sm[];
    uint32_t* Aq = (uint32_t*)sm + W_AQ;
    uint32_t* Bs = (uint32_t*)sm + W_BQ;
    float* Eb0 = sm + W_PAR;
    float* Eb1 = Eb0 + NPAD;
    float* A1s = Eb0 + 2*NPAD;
    float* A1z = Eb0 + 3*NPAD;
    float* Fb  = Eb0 + 4*NPAD;
    float* A2s = Eb0 + 5*NPAD;
    float* C2s = Eb0 + 6*NPAD;
    float* W30 = Eb0 + 7*NPAD;
    float* W31 = Eb0 + 8*NPAD;
    float* SUd = Eb0 + 9*NPAD;
    float* red0 = sm + W_RED;        // 256
    float* red1 = red0 + 256;        // 256
    int*   smaxi = (int*)(red0 + 512);

    int tid = threadIdx.x, wid = tid >> 5, lane = tid & 31;
    int j0 = blockIdx.x * 128, i = blockIdx.y, b = blockIdx.z;

    if (tid == 0) *smaxi = 0;

    // ---- B: copy pre-quantized s8 image, vectorized (L2-hot) ----
    {
        const uint4* src = (const uint4*)g_Bq;
        for (int t = tid; t < NPAD*(KW/4); t += 256) {
            int d = t / (KW/4), w4 = t % (KW/4);
            *(uint4*)(Bs + d*RSTR + 4*w4) = src[t];
        }
    }
    // ---- per-CTA folded params + analytic tile-max candidate ----
    if (tid < NPAD) SUd[tid] = g_Ud[tid];
    if (tid < DD) {
        float A1 = g_A1f[tid], C1 = g_C1f[tid];
        float bb = b1[tid];
        float e1 = fmaf(A1, g_Q1[(b*SS + i)*DD + tid] + bb, C1);
        float e0 = (i > 0) ? fmaf(A1, g_Q1[(b*SS + i - 1)*DD + tid] + bb, C1) : C1;
        float a1z = (i > 0) ? A1 : 0.f;
        Eb1[tid] = e1; Eb0[tid] = e0;
        A1s[tid] = A1; A1z[tid] = a1z;
        Fb[tid]  = g_b12[tid] + g_Q1[(b*SS + i)*DD + tid];
        A2s[tid] = g_A2f[tid];
        C2s[tid] = g_C2f[tid];
        W30[tid] = W3[2*tid];
        W31[tid] = W3[2*tid + 1];
        // tile upper bound from per-(b,c) K1 extremes (covers both signs of A1)
        float kx = fdec(g_K1mxE[b*DD + tid]);
        float kn = fdec(g_K1mnE[b*DD + tid]);
        float m = fmaxf(fmaxf(fmaxf(fmaf(a1z, kx, e0), fmaf(a1z, kn, e0)),
                              fmaxf(fmaf(A1,  kx, e1), fmaf(A1,  kn, e1))), 0.f);
        atomicMax(smaxi, __float_as_int(m));   // m >= 0: int compare valid
    }
    __syncthreads();

    float amax = __int_as_float(*smaxi);
    float s_a   = amax / 255.f;
    float inv_s = (amax > 0.f) ? 255.f / amax : 0.f;

    // ---- A generation: r1 on the fly -> u8 quantize -> packed words ----
    {
        int j = tid & 127, half = tid >> 7;
        const float* kcol = g_K1T + (size_t)b*DD*SS + j0 + j;
        uint32_t* arow = Aq + j*RSTR;
        #pragma unroll 5
        for (int w = half*25; w < half*25 + 25; w++) {
            int c0 = 2*w, c1 = 2*w + 1;
            float kv0 = kcol[(size_t)c0*SS];
            float kv1 = kcol[(size_t)c1*SS];
            float v00 = fmaxf(fmaf(A1z[c0], kv0, Eb0[c0]), 0.f);
            float v01 = fmaxf(fmaf(A1s[c0], kv0, Eb1[c0]), 0.f);
            float v10 = fmaxf(fmaf(A1z[c1], kv1, Eb0[c1]), 0.f);
            float v11 = fmaxf(fmaf(A1s[c1], kv1, Eb1[c1]), 0.f);
            uint32_t q0 = min(__float2uint_rn(v00 * inv_s), 255u);
            uint32_t q1 = min(__float2uint_rn(v01 * inv_s), 255u);
            uint32_t q2 = min(__float2uint_rn(v10 * inv_s), 255u);
            uint32_t q3 = min(__float2uint_rn(v11 * inv_s), 255u);
            arow[w] = q0 | (q1 << 8) | (q2 << 16) | (q3 << 24);
        }
        // zero K-pad words 50..55
        arow[50 + half*3]     = 0u;
        arow[50 + half*3 + 1] = 0u;
        arow[50 + half*3 + 2] = 0u;
    }
    __syncthreads();

    // ---- MMA mainloop: warp tile 16j x 104d, m16n8k32 u8.s8 ----
    int C[NT][4];
    #pragma unroll
    for (int nt = 0; nt < NT; nt++)
        #pragma unroll
        for (int r = 0; r < 4; r++) C[nt][r] = 0;

    {
        int ly = lane >> 2, lx = lane & 3;
        int jw = wid * 16;
        const uint32_t* arow0 = Aq + (jw + ly)*RSTR;
        const uint32_t* arow1 = Aq + (jw + ly + 8)*RSTR;
        const uint32_t* brow  = Bs + ly*RSTR;
        #pragma unroll
        for (int ks = 0; ks < KS32; ks++) {
            int kw = 8*ks;
            uint32_t a0 = arow0[kw + lx];
            uint32_t a1 = arow1[kw + lx];
            uint32_t a2 = arow0[kw + lx + 4];
            uint32_t a3 = arow1[kw + lx + 4];
            #pragma unroll
            for (int nt = 0; nt < NT; nt++) {
                uint32_t b0 = brow[nt*8*RSTR + kw + lx];
                uint32_t b1v = brow[nt*8*RSTR + kw + lx + 4];
                mma_u8s8(C[nt], a0, a1, a2, a3, b0, b1v);
            }
        }
    }
    __syncthreads();   // all warps done with Aq/Bs before staging overwrites

    // ---- dequant + stage to smem: Cs[j][d] stride CSTR (reuses Aq/Bs region) ----
    float* Cs = sm;
    {
        int ly = lane >> 2, lx = lane & 3;
        int jw = wid * 16;
        #pragma unroll
        for (int nt = 0; nt < NT; nt++) {
            int col = 8*nt + 2*lx;
            float u0 = s_a * SUd[col], u1 = s_a * SUd[col + 1];
            *(float2*)(Cs + (jw + ly    )*CSTR + col) =
                make_float2((float)C[nt][0] * u0, (float)C[nt][1] * u1);
            *(float2*)(Cs + (jw + ly + 8)*CSTR + col) =
                make_float2((float)C[nt][2] * u0, (float)C[nt][3] * u1);
        }
    }
    __syncthreads();

    // ---- epilogue: residual + bn2 + relu (local), conv3 partials P0/P1 ----
    {
        int jrow = tid & 127, dhalf = tid >> 7;
        const float* kcol = g_K1T + (size_t)b*DD*SS + j0 + jrow;
        float p0 = 0.f, p1 = 0.f;
        #pragma unroll 5
        for (int d = dhalf*50; d < dhalf*50 + 50; d++) {
            float t = Cs[jrow*CSTR + d] + Fb[d] + kcol[(size_t)d*SS];
            float val = fmaxf(fmaf(A2s[d], t, C2s[d]), 0.f);
            p0 = fmaf(W30[d], val, p0);
            p1 = fmaf(W31[d], val, p1);
        }
        red0[tid] = p0; red1[tid] = p1;
        __syncthreads();
        if (tid < 128) {
            g_P0[(size_t)(b*SS + i)*SS + j0 + tid] = red0[tid] + red0[tid + 128];
        } else {
            int j = tid - 128;
            g_P1[(size_t)(b*SS + i)*SS + j0 + j] = red1[j] + red1[j + 128];
        }
    }
}

// ============================================================
// Kernel 3: logits from P0/P1 + softmax(j) + attn@v. One block per (b, i).
// Shuffle-based reductions (2 syncthreads-phases instead of 16).
// Output: [ out (8*254*64) | attn (8*254*256) ]
// ============================================================
__global__ void attn_kernel(const float* __restrict__ b3, const float* __restrict__ v,
                            float* __restrict__ out) {
    int i = blockIdx.x, b = blockIdx.y;
    int tid = threadIdx.x;   // = j
    int wid = tid >> 5, lane = tid & 31;
    __shared__ float wred[8];
    __shared__ float attn_s[256];
    __shared__ float red[256];

    float logit = (b3[0] + g_P0[(size_t)(b*SS + i)*SS + tid]
                         + g_P1[(size_t)(b*SS + i + 1)*SS + tid]) * TEMP_INV;

    // warp max -> cross-warp max
    float m = logit;
    #pragma unroll
    for (int o = 16; o > 0; o >>= 1) m = fmaxf(m, __shfl_xor_sync(~0u, m, o));
    if (lane == 0) wred[wid] = m;
    __syncthreads();
    float mx = wred[0];
    #pragma unroll
    for (int w = 1; w < 8; w++) mx = fmaxf(mx, wred[w]);

    float p = __expf(logit - mx);
    // warp sum -> cross-warp sum
    float s = p;
    #pragma unroll
    for (int o = 16; o > 0; o >>= 1) s += __shfl_xor_sync(~0u, s, o);
    __syncthreads();              // wred reuse
    if (lane == 0) wred[wid] = s;
    __syncthreads();
    float tot = wred[0];
    #pragma unroll
    for (int w = 1; w < 8; w++) tot += wred[w];
    float inv = 1.f / tot;

    float a = p * inv;
    attn_s[tid] = a;
    out[(size_t)BB*SO*DIMQ + (size_t)(b*SO + i)*SS + tid] = a;
    __syncthreads();

    // out[b,i,t] = sum_j attn[j] * v[b,j,t]; 4 j-quarters x 64 t (coalesced on t)
    int t = tid & 63, g = tid >> 6;
    const float* vb = v + (size_t)b*SS*DIMQ + t;
    float acc = 0.f;
    #pragma unroll 4
    for (int j = g*64; j < g*64 + 64; j++) acc += attn_s[j] * vb[(size_t)j*DIMQ];
    red[tid] = acc; __syncthreads();
    if (g == 0)
        out[(size_t)(b*SO + i)*DIMQ + t] = red[t] + red[64+t] + red[128+t] + red[192+t];
}

// ============================================================
extern "C" void kernel_launch(void* const* d_in, const int* in_sizes, int n_in,
                              void* d_out, int out_size) {
    const float* q    = (const float*)d_in[0];
    const float* k    = (const float*)d_in[1];
    const float* v    = (const float*)d_in[2];
    const float* W1   = (const float*)d_in[3];
    const float* b1   = (const float*)d_in[4];
    const float* g1   = (const float*)d_in[5];
    const float* be1  = (const float*)d_in[6];
    const float* m1   = (const float*)d_in[7];
    const float* var1 = (const float*)d_in[8];
    const float* W2   = (const float*)d_in[9];
    const float* b2   = (const float*)d_in[10];
    const float* g2   = (const float*)d_in[11];
    const float* be2  = (const float*)d_in[12];
    const float* m2   = (const float*)d_in[13];
    const float* var2 = (const float*)d_in[14];
    const float* W3   = (const float*)d_in[15];
    const float* b3   = (const float*)d_in[16];
    float* out = (float*)d_out;

    cudaFuncSetAttribute(gemm2_mma, cudaFuncAttributeMaxDynamicSharedMemorySize,
                         SM_WORDS * (int)sizeof(float));

    params_kernel<<<1, 256>>>(W1, W2, b1, b2, g1, be1, m1, var1, g2, be2, m2, var2);
    prep_kernel  <<<dim3((SS*DD + 255)/256, BB, 2), 256>>>(q, k);
    gemm2_mma    <<<dim3(2, SA, BB), 256, SM_WORDS*sizeof(float)>>>(b1, W3);
    attn_kernel  <<<dim3(SO, BB), 256>>>(b3, v, out);
}